// round 1
// baseline (speedup 1.0000x reference)
#include <cuda_runtime.h>
#include <math.h>

#define BATCH 8192
#define PIX 784
#define WIRES 10
#define DIM 1024
#define QDEPTH 20
#define NGATES (QDEPTH * WIRES)   // 200

// ---------------- scratch (device globals; no runtime allocation) ----------------
__device__ float  g_ca[BATCH * WIRES];          // cos(theta/2)
__device__ float  g_sa[BATCH * WIRES];          // sin(theta/2)
__device__ float2 g_gates[NGATES * 4];          // 200 Rot gates, 2x2 complex each
__device__ float  g_Ure[DIM * DIM];             // U real, stored [i_in * 1024 + j_out]
__device__ float  g_Uim[DIM * DIM];             // U imag
__device__ float  g_S[(size_t)BATCH * DIM];     // product states, [b*1024 + i]

// ---------------- kernel 1: angles = x @ W^T + b -> cos/sin of half-angle --------
__global__ __launch_bounds__(256) void k_angles(const float* __restrict__ x,
                                                const float* __restrict__ W,
                                                const float* __restrict__ bias) {
    int warp = (blockIdx.x * blockDim.x + threadIdx.x) >> 5;
    int lane = threadIdx.x & 31;
    if (warp >= BATCH) return;
    const float* xr = x + (size_t)warp * PIX;
    float acc[WIRES];
#pragma unroll
    for (int w = 0; w < WIRES; w++) acc[w] = 0.f;
    for (int p = lane; p < PIX; p += 32) {
        float xv = xr[p];
#pragma unroll
        for (int w = 0; w < WIRES; w++)
            acc[w] = fmaf(xv, __ldg(&W[w * PIX + p]), acc[w]);
    }
#pragma unroll
    for (int w = 0; w < WIRES; w++) {
        float v = acc[w];
#pragma unroll
        for (int o = 16; o; o >>= 1) v += __shfl_xor_sync(0xffffffffu, v, o);
        acc[w] = v;
    }
    if (lane == 0) {
#pragma unroll
        for (int w = 0; w < WIRES; w++) {
            float h = 0.5f * (acc[w] + bias[w]);
            g_ca[warp * WIRES + w] = cosf(h);
            g_sa[warp * WIRES + w] = sinf(h);
        }
    }
}

// ---------------- kernel 2: Rot(phi,theta,omega) gate matrices -------------------
// m00 = e^{-i(phi+om)/2} c ; m01 = -e^{+i(phi-om)/2} s
// m10 = e^{-i(phi-om)/2} s ; m11 = e^{+i(phi+om)/2} c
__global__ void k_gates(const float* __restrict__ qw) {
    int g = blockIdx.x * blockDim.x + threadIdx.x;
    if (g >= NGATES) return;
    float phi = qw[g * 3 + 0], th = qw[g * 3 + 1], om = qw[g * 3 + 2];
    float c = cosf(0.5f * th), s = sinf(0.5f * th);
    float A = 0.5f * (phi + om), B = 0.5f * (phi - om);
    float cA = cosf(A), sA = sinf(A), cB = cosf(B), sB = sinf(B);
    g_gates[g * 4 + 0] = make_float2(cA * c, -sA * c);
    g_gates[g * 4 + 1] = make_float2(-cB * s, -sB * s);
    g_gates[g * 4 + 2] = make_float2(cB * s, -sB * s);
    g_gates[g * 4 + 3] = make_float2(cA * c,  sA * c);
}

// ---------------- kernel 3: build U column-by-column -----------------------------
// Block `col` simulates the circuit on basis state |col>. Wire w <-> bit (9-w).
__global__ __launch_bounds__(512) void k_buildU() {
    __shared__ float2 st[DIM];
    __shared__ float2 gs[NGATES * 4];
    const int t = threadIdx.x;          // 0..511
    const int col = blockIdx.x;

    for (int i = t; i < NGATES * 4; i += 512) gs[i] = g_gates[i];
    st[t]       = make_float2(t == col ? 1.f : 0.f, 0.f);
    st[t + 512] = make_float2((t + 512) == col ? 1.f : 0.f, 0.f);
    __syncthreads();

    for (int l = 0; l < QDEPTH; l++) {
        // Rot on every wire
        for (int w = 0; w < WIRES; w++) {
            const int gi = (l * WIRES + w) * 4;
            const float2 g00 = gs[gi + 0], g01 = gs[gi + 1];
            const float2 g10 = gs[gi + 2], g11 = gs[gi + 3];
            const int mask = 1 << (9 - w);
            const int low = t & (mask - 1);
            const int i0 = ((t & ~(mask - 1)) << 1) | low;
            const int i1 = i0 | mask;
            const float2 a0 = st[i0], a1 = st[i1];
            float2 n0, n1;
            n0.x = g00.x * a0.x - g00.y * a0.y + g01.x * a1.x - g01.y * a1.y;
            n0.y = g00.x * a0.y + g00.y * a0.x + g01.x * a1.y + g01.y * a1.x;
            n1.x = g10.x * a0.x - g10.y * a0.y + g11.x * a1.x - g11.y * a1.y;
            n1.y = g10.x * a0.y + g10.y * a0.x + g11.x * a1.y + g11.y * a1.x;
            st[i0] = n0; st[i1] = n1;
            __syncthreads();
        }
        // CNOT ring, composed into one self-inverse-per-step permutation gather:
        // v_final[j] = v[sigma_0(sigma_1(...sigma_9(j)))]
        const int r = (l % (WIRES - 1)) + 1;
        int p0 = t, p1 = t + 512;
#pragma unroll
        for (int w = WIRES - 1; w >= 0; w--) {
            const int cm = 1 << (9 - w);
            const int tm = 1 << (9 - ((w + r) % WIRES));
            if (p0 & cm) p0 ^= tm;
            if (p1 & cm) p1 ^= tm;
        }
        const float2 v0 = st[p0], v1 = st[p1];
        __syncthreads();
        st[t] = v0; st[t + 512] = v1;
        __syncthreads();
    }
    // store U[j, col] at g_U*[col*1024 + j]  (j contiguous -> GEMM B loads coalesce)
    g_Ure[col * DIM + t]       = st[t].x;
    g_Uim[col * DIM + t]       = st[t].y;
    g_Ure[col * DIM + t + 512] = st[t + 512].x;
    g_Uim[col * DIM + t + 512] = st[t + 512].y;
}

// ---------------- kernel 4: product state S[b,i] ---------------------------------
__global__ __launch_bounds__(256) void k_S() {
    __shared__ float cL[32], cR[32];
    const int b = blockIdx.x;
    const int t = threadIdx.x;
    if (t < 32) {
        float p = 1.f;
#pragma unroll
        for (int w = 0; w < 5; w++) {
            int bit = (t >> (4 - w)) & 1;
            p *= bit ? g_sa[b * WIRES + w] : g_ca[b * WIRES + w];
        }
        cL[t] = p;
    } else if (t < 64) {
        int l = t - 32;
        float p = 1.f;
#pragma unroll
        for (int w = 0; w < 5; w++) {
            int bit = (l >> (4 - w)) & 1;
            p *= bit ? g_sa[b * WIRES + 5 + w] : g_ca[b * WIRES + 5 + w];
        }
        cR[l] = p;
    }
    __syncthreads();
#pragma unroll
    for (int k = 0; k < 4; k++) {
        int i = t + 256 * k;
        g_S[(size_t)b * DIM + i] = cL[i >> 5] * cR[i & 31];
    }
}

// ---------------- kernel 5: GEMM 8192x784x1024 (real x complex) + epilogue -------
// BM=128, BN=64, BK=16, 256 threads, thread tile 8x4, Re+Im accumulators
__global__ __launch_bounds__(256) void k_gemm(float* __restrict__ out) {
    __shared__ float  As[2][16][132];
    __shared__ float4 Bre[2][16][16];
    __shared__ float4 Bim[2][16][16];

    const int tid = threadIdx.x;
    const int m0 = blockIdx.x * 128;
    const int n0 = blockIdx.y * 64;

    const int rg = tid >> 4;   // 0..15
    const int cg = tid & 15;   // 0..15

    // A tile load mapping: 128 rows x 4 float4-quads
    const int arow = tid >> 2;  // 0..63 (and +64)
    const int akq  = tid & 3;   // 0..3
    // B tile load mapping: 16 k-rows x 16 float4s
    const int bk  = tid >> 4;   // 0..15
    const int bjq = tid & 15;   // 0..15
    const int j4  = n0 + bjq * 4;
    const bool jok = (j4 < PIX);

    const float* A0 = g_S + (size_t)(m0 + arow) * DIM + akq * 4;
    const float* A1 = A0 + (size_t)64 * DIM;

    const float4 z4 = make_float4(0.f, 0.f, 0.f, 0.f);
    float4 ar0, ar1, br, bi;

    // prologue: stage 0
    ar0 = *(const float4*)A0;
    ar1 = *(const float4*)A1;
    br = jok ? *(const float4*)(g_Ure + (size_t)bk * DIM + j4) : z4;
    bi = jok ? *(const float4*)(g_Uim + (size_t)bk * DIM + j4) : z4;
    As[0][akq * 4 + 0][arow] = ar0.x;  As[0][akq * 4 + 1][arow] = ar0.y;
    As[0][akq * 4 + 2][arow] = ar0.z;  As[0][akq * 4 + 3][arow] = ar0.w;
    As[0][akq * 4 + 0][arow + 64] = ar1.x;  As[0][akq * 4 + 1][arow + 64] = ar1.y;
    As[0][akq * 4 + 2][arow + 64] = ar1.z;  As[0][akq * 4 + 3][arow + 64] = ar1.w;
    Bre[0][bk][bjq] = br;
    Bim[0][bk][bjq] = bi;
    __syncthreads();

    float cr[8][4], ci[8][4];
#pragma unroll
    for (int i = 0; i < 8; i++)
#pragma unroll
        for (int j = 0; j < 4; j++) { cr[i][j] = 0.f; ci[i][j] = 0.f; }

    for (int kt = 0; kt < 64; kt++) {
        const int cur = kt & 1;
        if (kt < 63) {
            const int kn = (kt + 1) * 16;
            ar0 = *(const float4*)(A0 + kn);
            ar1 = *(const float4*)(A1 + kn);
            br = jok ? *(const float4*)(g_Ure + (size_t)(kn + bk) * DIM + j4) : z4;
            bi = jok ? *(const float4*)(g_Uim + (size_t)(kn + bk) * DIM + j4) : z4;
        }
#pragma unroll
        for (int kk = 0; kk < 16; kk++) {
            const float4 a0 = *(const float4*)&As[cur][kk][rg * 8];
            const float4 a1 = *(const float4*)&As[cur][kk][rg * 8 + 4];
            const float4 b0 = Bre[cur][kk][cg];
            const float4 b1 = Bim[cur][kk][cg];
            const float av[8]  = {a0.x, a0.y, a0.z, a0.w, a1.x, a1.y, a1.z, a1.w};
            const float brv[4] = {b0.x, b0.y, b0.z, b0.w};
            const float biv[4] = {b1.x, b1.y, b1.z, b1.w};
#pragma unroll
            for (int i = 0; i < 8; i++)
#pragma unroll
                for (int j = 0; j < 4; j++) {
                    cr[i][j] = fmaf(av[i], brv[j], cr[i][j]);
                    ci[i][j] = fmaf(av[i], biv[j], ci[i][j]);
                }
        }
        if (kt < 63) {
            const int nxt = cur ^ 1;
            As[nxt][akq * 4 + 0][arow] = ar0.x;  As[nxt][akq * 4 + 1][arow] = ar0.y;
            As[nxt][akq * 4 + 2][arow] = ar0.z;  As[nxt][akq * 4 + 3][arow] = ar0.w;
            As[nxt][akq * 4 + 0][arow + 64] = ar1.x;  As[nxt][akq * 4 + 1][arow + 64] = ar1.y;
            As[nxt][akq * 4 + 2][arow + 64] = ar1.z;  As[nxt][akq * 4 + 3][arow + 64] = ar1.w;
            Bre[nxt][bk][bjq] = br;
            Bim[nxt][bk][bjq] = bi;
            __syncthreads();
        }
    }

    // epilogue: out = min(|amp|^2 * 784, 1)
    const int mbase = m0 + rg * 8;
#pragma unroll
    for (int i = 0; i < 8; i++) {
        const size_t orow = (size_t)(mbase + i) * PIX;
#pragma unroll
        for (int j = 0; j < 4; j++) {
            const int gj = n0 + cg * 4 + j;
            if (gj < PIX) {
                const float v = cr[i][j] * cr[i][j] + ci[i][j] * ci[i][j];
                out[orow + gj] = fminf(v * (float)PIX, 1.0f);
            }
        }
    }
}

// ---------------- launch ----------------------------------------------------------
extern "C" void kernel_launch(void* const* d_in, const int* in_sizes, int n_in,
                              void* d_out, int out_size) {
    const float* x  = (const float*)d_in[0];
    const float* W  = (const float*)d_in[1];
    const float* b  = (const float*)d_in[2];
    const float* qw = (const float*)d_in[3];
    float* out = (float*)d_out;

    k_angles<<<BATCH / 8, 256>>>(x, W, b);   // 8 warps/block, one warp per batch row
    k_gates<<<1, 256>>>(qw);
    k_buildU<<<DIM, 512>>>();
    k_S<<<BATCH, 256>>>();
    dim3 grid(BATCH / 128, (PIX + 63) / 64); // 64 x 13
    k_gemm<<<grid, 256>>>(out);
}

// round 4
// speedup vs baseline: 1.8537x; 1.8537x over previous
#include <cuda_runtime.h>
#include <cuda_bf16.h>
#include <math.h>
#include <stdint.h>

#define BATCH 8192
#define PIX 784
#define WIRES 10
#define DIM 1024
#define QDEPTH 20
#define NGATES (QDEPTH * WIRES)   // 200

#define KBIG 3072                 // [hi | lo | hi] concatenated K
#define NBIG 1664                 // 832 j-slots x (re,im) interleaved (13 tiles of 128)
#define BKT  64                   // K per smem tile (64 bf16 = 128B = SW128 row)
#define NKT  (KBIG / BKT)         // 48

// ---------------- scratch ----------------
__device__ float  g_ca[BATCH * WIRES];
__device__ float  g_sa[BATCH * WIRES];
__device__ float2 g_gates[NGATES * 4];
__device__ float  g_Ure[DIM * DIM];             // [k][j]
__device__ float  g_Uim[DIM * DIM];             // [k][j]
__device__ __nv_bfloat16 g_As[(size_t)BATCH * KBIG];   // A' [m][k]
__device__ __nv_bfloat16 g_Bb[(size_t)NBIG * KBIG];    // B' [n][k]

// ---------------- helpers ----------------
__device__ __forceinline__ uint32_t smem_u32(const void* p) {
    uint32_t a;
    asm("{ .reg .u64 t; cvta.to.shared.u64 t, %1; cvt.u32.u64 %0, t; }" : "=r"(a) : "l"(p));
    return a;
}

__device__ __forceinline__ void cp_async16(uint32_t dst, const void* src) {
    asm volatile("cp.async.cg.shared.global [%0], [%1], 16;" :: "r"(dst), "l"(src));
}
#define CP_COMMIT() asm volatile("cp.async.commit_group;" ::: "memory")
#define CP_WAIT2()  asm volatile("cp.async.wait_group 2;" ::: "memory")

__device__ __forceinline__ void ldsm_x4(uint32_t* r, uint32_t addr) {
    asm volatile("ldmatrix.sync.aligned.m8n8.x4.shared.b16 {%0,%1,%2,%3}, [%4];"
                 : "=r"(r[0]), "=r"(r[1]), "=r"(r[2]), "=r"(r[3]) : "r"(addr));
}
__device__ __forceinline__ void mma16816(float* d, const uint32_t* a, const uint32_t* b) {
    asm volatile(
        "mma.sync.aligned.m16n8k16.row.col.f32.bf16.bf16.f32 "
        "{%0,%1,%2,%3}, {%4,%5,%6,%7}, {%8,%9}, {%0,%1,%2,%3};"
        : "+f"(d[0]), "+f"(d[1]), "+f"(d[2]), "+f"(d[3])
        : "r"(a[0]), "r"(a[1]), "r"(a[2]), "r"(a[3]), "r"(b[0]), "r"(b[1]));
}

// ---------------- kernel 1: angles ----------------
__global__ __launch_bounds__(256) void k_angles(const float* __restrict__ x,
                                                const float* __restrict__ W,
                                                const float* __restrict__ bias) {
    int warp = (blockIdx.x * blockDim.x + threadIdx.x) >> 5;
    int lane = threadIdx.x & 31;
    if (warp >= BATCH) return;
    const float* xr = x + (size_t)warp * PIX;
    float acc[WIRES];
#pragma unroll
    for (int w = 0; w < WIRES; w++) acc[w] = 0.f;
    for (int p = lane; p < PIX; p += 32) {
        float xv = xr[p];
#pragma unroll
        for (int w = 0; w < WIRES; w++)
            acc[w] = fmaf(xv, __ldg(&W[w * PIX + p]), acc[w]);
    }
#pragma unroll
    for (int w = 0; w < WIRES; w++) {
        float v = acc[w];
#pragma unroll
        for (int o = 16; o; o >>= 1) v += __shfl_xor_sync(0xffffffffu, v, o);
        acc[w] = v;
    }
    if (lane == 0) {
#pragma unroll
        for (int w = 0; w < WIRES; w++) {
            float h = 0.5f * (acc[w] + bias[w]);
            g_ca[warp * WIRES + w] = cosf(h);
            g_sa[warp * WIRES + w] = sinf(h);
        }
    }
}

// ---------------- kernel 2: Rot gates ----------------
__global__ void k_gates(const float* __restrict__ qw) {
    int g = blockIdx.x * blockDim.x + threadIdx.x;
    if (g >= NGATES) return;
    float phi = qw[g * 3 + 0], th = qw[g * 3 + 1], om = qw[g * 3 + 2];
    float c = cosf(0.5f * th), s = sinf(0.5f * th);
    float A = 0.5f * (phi + om), B = 0.5f * (phi - om);
    float cA = cosf(A), sA = sinf(A), cB = cosf(B), sB = sinf(B);
    g_gates[g * 4 + 0] = make_float2(cA * c, -sA * c);
    g_gates[g * 4 + 1] = make_float2(-cB * s, -sB * s);
    g_gates[g * 4 + 2] = make_float2(cB * s, -sB * s);
    g_gates[g * 4 + 3] = make_float2(cA * c,  sA * c);
}

// ---------------- kernel 3: build U (column = basis input k) ----------------
__global__ __launch_bounds__(512) void k_buildU() {
    __shared__ float2 st[DIM];
    __shared__ float2 gs[NGATES * 4];
    const int t = threadIdx.x;
    const int col = blockIdx.x;

    for (int i = t; i < NGATES * 4; i += 512) gs[i] = g_gates[i];
    st[t]       = make_float2(t == col ? 1.f : 0.f, 0.f);
    st[t + 512] = make_float2((t + 512) == col ? 1.f : 0.f, 0.f);
    __syncthreads();

    for (int l = 0; l < QDEPTH; l++) {
        for (int w = 0; w < WIRES; w++) {
            const int gi = (l * WIRES + w) * 4;
            const float2 g00 = gs[gi + 0], g01 = gs[gi + 1];
            const float2 g10 = gs[gi + 2], g11 = gs[gi + 3];
            const int mask = 1 << (9 - w);
            const int low = t & (mask - 1);
            const int i0 = ((t & ~(mask - 1)) << 1) | low;
            const int i1 = i0 | mask;
            const float2 a0 = st[i0], a1 = st[i1];
            float2 n0, n1;
            n0.x = g00.x * a0.x - g00.y * a0.y + g01.x * a1.x - g01.y * a1.y;
            n0.y = g00.x * a0.y + g00.y * a0.x + g01.x * a1.y + g01.y * a1.x;
            n1.x = g10.x * a0.x - g10.y * a0.y + g11.x * a1.x - g11.y * a1.y;
            n1.y = g10.x * a0.y + g10.y * a0.x + g11.x * a1.y + g11.y * a1.x;
            st[i0] = n0; st[i1] = n1;
            __syncthreads();
        }
        const int r = (l % (WIRES - 1)) + 1;
        int p0 = t, p1 = t + 512;
#pragma unroll
        for (int w = WIRES - 1; w >= 0; w--) {
            const int cm = 1 << (9 - w);
            const int tm = 1 << (9 - ((w + r) % WIRES));
            if (p0 & cm) p0 ^= tm;
            if (p1 & cm) p1 ^= tm;
        }
        const float2 v0 = st[p0], v1 = st[p1];
        __syncthreads();
        st[t] = v0; st[t + 512] = v1;
        __syncthreads();
    }
    g_Ure[col * DIM + t]       = st[t].x;
    g_Uim[col * DIM + t]       = st[t].y;
    g_Ure[col * DIM + t + 512] = st[t + 512].x;
    g_Uim[col * DIM + t + 512] = st[t + 512].y;
}

// ---------------- kernel 4: A' = split product state ----------------
__global__ __launch_bounds__(256) void k_A() {
    __shared__ float cL[32], cR[32];
    const int b = blockIdx.x;
    const int t = threadIdx.x;
    if (t < 32) {
        float p = 1.f;
#pragma unroll
        for (int w = 0; w < 5; w++) {
            int bit = (t >> (4 - w)) & 1;
            p *= bit ? g_sa[b * WIRES + w] : g_ca[b * WIRES + w];
        }
        cL[t] = p;
    } else if (t < 64) {
        int l = t - 32;
        float p = 1.f;
#pragma unroll
        for (int w = 0; w < 5; w++) {
            int bit = (l >> (4 - w)) & 1;
            p *= bit ? g_sa[b * WIRES + 5 + w] : g_ca[b * WIRES + 5 + w];
        }
        cR[l] = p;
    }
    __syncthreads();
    __nv_bfloat16* row = g_As + (size_t)b * KBIG;
#pragma unroll
    for (int kq = 0; kq < 4; kq++) {
        int i = t + 256 * kq;
        float s = cL[i >> 5] * cR[i & 31];
        __nv_bfloat16 hi = __float2bfloat16(s);
        __nv_bfloat16 lo = __float2bfloat16(s - __bfloat162float(hi));
        row[i]        = hi;
        row[i + 1024] = lo;
        row[i + 2048] = hi;
    }
}

// ---------------- kernel 5: B' = transpose + split U ----------------
// grid (32 ktiles, 26 jtiles of 32), block (32,8); j in [0, 832)
__global__ void k_B() {
    __shared__ float sre[32][33], sim[32][33];
    const int k0 = blockIdx.x * 32, j0 = blockIdx.y * 32;
    const int tx = threadIdx.x, ty = threadIdx.y;
    for (int r = ty; r < 32; r += 8) {
        sre[r][tx] = g_Ure[(k0 + r) * DIM + j0 + tx];
        sim[r][tx] = g_Uim[(k0 + r) * DIM + j0 + tx];
    }
    __syncthreads();
    for (int jl = ty; jl < 32; jl += 8) {
        int j = j0 + jl, k = k0 + tx;
        float vr = sre[tx][jl], vi = sim[tx][jl];
        __nv_bfloat16 hr = __float2bfloat16(vr);
        __nv_bfloat16 lr = __float2bfloat16(vr - __bfloat162float(hr));
        __nv_bfloat16 hi = __float2bfloat16(vi);
        __nv_bfloat16 li = __float2bfloat16(vi - __bfloat162float(hi));
        __nv_bfloat16* rR = g_Bb + (size_t)(2 * j) * KBIG;
        __nv_bfloat16* rI = rR + KBIG;
        rR[k] = hr; rR[k + 1024] = hr; rR[k + 2048] = lr;
        rI[k] = hi; rI[k + 1024] = hi; rI[k + 2048] = li;
    }
}

// ---------------- kernel 6: mma.sync bf16 GEMM + epilogue ----------------
// BM=128, BN=128, BK=64, 3-stage cp.async pipeline, 8 warps (2 M x 4 N),
// warp tile 64x32, mma.m16n8k16. smem stage = 32KB (A 16K + B 16K).
#define STAGE_BYTES 32768
#define GEMM_SMEM   (3 * STAGE_BYTES)   // 98304

__device__ __forceinline__ void load_tile(uint32_t sbase, int stage, int kt,
                                          const __nv_bfloat16* gA,
                                          const __nv_bfloat16* gB, int tid) {
    const uint32_t aS = sbase + stage * STAGE_BYTES;
    const uint32_t bS = aS + 16384;
    const int r0 = tid >> 3;        // 0..31
    const int c  = tid & 7;         // 0..7 (16B chunks)
    const uint32_t cx = (uint32_t)(c * 16);
#pragma unroll
    for (int p = 0; p < 4; p++) {
        const int row = p * 32 + r0;
        const uint32_t off = (uint32_t)(row * 128) + (cx ^ ((row & 7) * 16));
        cp_async16(aS + off, gA + (size_t)row * KBIG + (size_t)kt * BKT + c * 8);
    }
#pragma unroll
    for (int p = 0; p < 4; p++) {
        const int row = p * 32 + r0;
        const uint32_t off = (uint32_t)(row * 128) + (cx ^ ((row & 7) * 16));
        cp_async16(bS + off, gB + (size_t)row * KBIG + (size_t)kt * BKT + c * 8);
    }
}

__global__ __launch_bounds__(256, 2) void k_gemm(float* __restrict__ out) {
    extern __shared__ char smem[];
    const uint32_t sbase = smem_u32(smem);
    const int tid = threadIdx.x;
    const int wid = tid >> 5, lane = tid & 31;
    const int wm = wid & 1, wn = wid >> 1;      // 2 x 4 warp grid
    const int m0 = blockIdx.x * 128;
    const int n0 = blockIdx.y * 128;

    const __nv_bfloat16* gA = g_As + (size_t)m0 * KBIG;
    const __nv_bfloat16* gB = g_Bb + (size_t)n0 * KBIG;

    float acc[4][4][4];
#pragma unroll
    for (int i = 0; i < 4; i++)
#pragma unroll
        for (int j = 0; j < 4; j++)
#pragma unroll
            for (int q = 0; q < 4; q++) acc[i][j][q] = 0.f;

    // prologue: stages 0,1
    load_tile(sbase, 0, 0, gA, gB, tid); CP_COMMIT();
    load_tile(sbase, 1, 1, gA, gB, tid); CP_COMMIT();

    // per-lane ldmatrix in-tile offsets (swizzled)
    const int a_row = wm * 64 + (lane & 7) + ((lane >> 3) & 1) * 8;
    const uint32_t a_kx = ((lane >> 4) & 1) * 16;
    const int b_row = wn * 32 + (lane & 7) + ((lane >> 4) & 1) * 8;
    const uint32_t b_kx = ((lane >> 3) & 1) * 16;

    int stage = 0;
    for (int kt = 0; kt < NKT; kt++) {
        if (kt + 2 < NKT) load_tile(sbase, (stage + 2) % 3, kt + 2, gA, gB, tid);
        CP_COMMIT();
        CP_WAIT2();
        __syncthreads();

        const uint32_t aS = sbase + stage * STAGE_BYTES;
        const uint32_t bS = aS + 16384;
#pragma unroll
        for (int ks = 0; ks < 4; ks++) {
            uint32_t afr[4][4], bfr[2][4];
#pragma unroll
            for (int mf = 0; mf < 4; mf++) {
                const int row = a_row + mf * 16;
                const uint32_t kb = (uint32_t)(ks * 32) + a_kx;
                ldsm_x4(afr[mf], aS + (uint32_t)(row * 128) + (kb ^ ((row & 7) * 16)));
            }
#pragma unroll
            for (int nf2 = 0; nf2 < 2; nf2++) {
                const int row = b_row + nf2 * 16;
                const uint32_t kb = (uint32_t)(ks * 32) + b_kx;
                ldsm_x4(bfr[nf2], bS + (uint32_t)(row * 128) + (kb ^ ((row & 7) * 16)));
            }
#pragma unroll
            for (int mf = 0; mf < 4; mf++)
#pragma unroll
                for (int nf = 0; nf < 4; nf++)
                    mma16816(acc[mf][nf], afr[mf], &bfr[nf >> 1][(nf & 1) * 2]);
        }
        __syncthreads();
        stage = (stage + 1) % 3;
    }

    // epilogue: c-fragment reg pair (c0,c1) = (re,im) of one pixel; (c2,c3) = row+8
    const int jbase = (n0 >> 1) + wn * 16;
    const int rbase = m0 + wm * 64 + (lane >> 2);
    const int jq = lane & 3;
#pragma unroll
    for (int mf = 0; mf < 4; mf++) {
#pragma unroll
        for (int nf = 0; nf < 4; nf++) {
            const int j = jbase + nf * 4 + jq;
            if (j < PIX) {
                const float re0 = acc[mf][nf][0], im0 = acc[mf][nf][1];
                const float re1 = acc[mf][nf][2], im1 = acc[mf][nf][3];
                out[(size_t)(rbase + mf * 16) * PIX + j] =
                    fminf((re0 * re0 + im0 * im0) * (float)PIX, 1.0f);
                out[(size_t)(rbase + mf * 16 + 8) * PIX + j] =
                    fminf((re1 * re1 + im1 * im1) * (float)PIX, 1.0f);
            }
        }
    }
}

// ---------------- launch ----------------
extern "C" void kernel_launch(void* const* d_in, const int* in_sizes, int n_in,
                              void* d_out, int out_size) {
    const float* x  = (const float*)d_in[0];
    const float* W  = (const float*)d_in[1];
    const float* b  = (const float*)d_in[2];
    const float* qw = (const float*)d_in[3];
    float* out = (float*)d_out;

    cudaFuncSetAttribute(k_gemm, cudaFuncAttributeMaxDynamicSharedMemorySize, GEMM_SMEM);

    k_angles<<<BATCH / 8, 256>>>(x, W, b);
    k_gates<<<1, 256>>>(qw);
    k_buildU<<<DIM, 512>>>();
    k_A<<<BATCH, 256>>>();
    dim3 gB(32, 26);
    k_B<<<gB, dim3(32, 8)>>>();
    dim3 gg(BATCH / 128, NBIG / 128);   // 64 x 13
    k_gemm<<<gg, 256, GEMM_SMEM>>>(out);
}